// round 16
// baseline (speedup 1.0000x reference)
#include <cuda_runtime.h>
#include <cuda_bf16.h>
#include <cstdint>

// ===========================================================================
// Tree-RNN round 15:
//  - leaf GEMM + prep + tree_stage1: byte-identical to the 161.2us version.
//  - tree_stage2/3: weights staged into dynamic smem once per kernel (the
//    per-launch L1D flush made the per-iteration weight __ldg a serial
//    L2-latency chain on tiny grids); levels then read weights via LDS.
// ===========================================================================

typedef unsigned long long ull;

// ----------------------------- scratch ------------------------------------
__device__ __nv_bfloat16 g_Bhi[128 * 4096];
__device__ __nv_bfloat16 g_Blo[128 * 4096];
__device__ float g_Wq[50 * 100 * 4];
__device__ float g_h0[8192 * 100];
__device__ float g_T1[100 * 256];
__device__ float g_T2[100 * 8];

// ----------------------------- helpers ------------------------------------
__device__ __forceinline__ void cp16(uint32_t saddr, const void* g) {
    asm volatile("cp.async.cg.shared.global [%0], [%1], 16;" :: "r"(saddr), "l"(g));
}
__device__ __forceinline__ void cp_commit() { asm volatile("cp.async.commit_group;"); }
__device__ __forceinline__ void cp_wait0()  { asm volatile("cp.async.wait_group 0;"); }

__device__ __forceinline__ void ldsm_x4(uint32_t& r0, uint32_t& r1, uint32_t& r2,
                                        uint32_t& r3, uint32_t addr) {
    asm volatile("ldmatrix.sync.aligned.m8n8.x4.shared.b16 {%0,%1,%2,%3}, [%4];"
                 : "=r"(r0), "=r"(r1), "=r"(r2), "=r"(r3) : "r"(addr));
}
__device__ __forceinline__ void mma16816(float* c, const uint32_t* a, const uint32_t* b) {
    asm volatile(
        "mma.sync.aligned.m16n8k16.row.col.f32.bf16.bf16.f32 "
        "{%0,%1,%2,%3}, {%4,%5,%6,%7}, {%8,%9}, {%0,%1,%2,%3};"
        : "+f"(c[0]), "+f"(c[1]), "+f"(c[2]), "+f"(c[3])
        : "r"(a[0]), "r"(a[1]), "r"(a[2]), "r"(a[3]), "r"(b[0]), "r"(b[1]));
}

__device__ __forceinline__ void split8(float4 a, float4 b, uint4& hv, uint4& lv) {
    __nv_bfloat162 h0 = __float22bfloat162_rn(make_float2(a.x, a.y));
    __nv_bfloat162 h1 = __float22bfloat162_rn(make_float2(a.z, a.w));
    __nv_bfloat162 h2 = __float22bfloat162_rn(make_float2(b.x, b.y));
    __nv_bfloat162 h3 = __float22bfloat162_rn(make_float2(b.z, b.w));
    float2 f0 = __bfloat1622float2(h0), f1 = __bfloat1622float2(h1);
    float2 f2 = __bfloat1622float2(h2), f3 = __bfloat1622float2(h3);
    __nv_bfloat162 l0 = __float22bfloat162_rn(make_float2(a.x - f0.x, a.y - f0.y));
    __nv_bfloat162 l1 = __float22bfloat162_rn(make_float2(a.z - f1.x, a.w - f1.y));
    __nv_bfloat162 l2 = __float22bfloat162_rn(make_float2(b.x - f2.x, b.y - f2.y));
    __nv_bfloat162 l3 = __float22bfloat162_rn(make_float2(b.z - f3.x, b.w - f3.y));
    hv = make_uint4(*(uint32_t*)&h0, *(uint32_t*)&h1, *(uint32_t*)&h2, *(uint32_t*)&h3);
    lv = make_uint4(*(uint32_t*)&l0, *(uint32_t*)&l1, *(uint32_t*)&l2, *(uint32_t*)&l3);
}

__device__ __forceinline__ ull pack2(float lo, float hi) {
    ull r;
    asm("mov.b64 %0, {%1, %2};" : "=l"(r) : "f"(lo), "f"(hi));
    return r;
}
__device__ __forceinline__ void fma2(ull& d, ull a, ull b) {
    asm("fma.rn.f32x2 %0, %1, %2, %0;" : "+l"(d) : "l"(a), "l"(b));
}
__device__ __forceinline__ void unpack2(ull v, float& lo, float& hi) {
    asm("mov.b64 {%0, %1}, %2;" : "=f"(lo), "=f"(hi) : "l"(v));
}

// ----------------------------- prep (merged) -------------------------------
__global__ void prep_all(const float* __restrict__ We,
                         __nv_bfloat16* __restrict__ bhi,
                         __nv_bfloat16* __restrict__ blo,
                         const float* __restrict__ W,
                         float* __restrict__ Wq) {
    int idx = blockIdx.x * blockDim.x + threadIdx.x;
    if (idx < 128 * 4096) {
        int n = idx >> 12;
        float v = (n < 100) ? We[idx] : 0.0f;
        __nv_bfloat16 h = __float2bfloat16(v);
        bhi[idx] = h;
        blo[idx] = __float2bfloat16(v - __bfloat162float(h));
    } else if (idx < 128 * 4096 + 5000) {
        int i = idx - 128 * 4096;
        int kk = i / 100, n = i % 100;
        float4 q;
        q.x = W[n * 200 + 2 * kk];
        q.y = W[n * 200 + 100 + 2 * kk];
        q.z = W[n * 200 + 2 * kk + 1];
        q.w = W[n * 200 + 101 + 2 * kk];
        *(float4*)(Wq + i * 4) = q;
    }
}

// ----------------------------- leaf GEMM (proven config) -------------------
#define AROWB     144
#define S_AHI     0
#define S_ALO     (64 * AROWB)
#define S_BHI     (2 * 64 * AROWB)
#define S_BLO     (S_BHI + 128 * AROWB)
#define LSTAGE    (S_BLO + 128 * AROWB)     // 55296
#define LEAF_SMEM (2 * LSTAGE)              // 110592

__global__ __launch_bounds__(512)
void leaf_gemm_mma(const float* __restrict__ A,
                   const __nv_bfloat16* __restrict__ Bhi,
                   const __nv_bfloat16* __restrict__ Blo,
                   const float* __restrict__ bias,
                   float* __restrict__ C) {
    extern __shared__ char smem[];
    const uint32_t sbase = (uint32_t)__cvta_generic_to_shared(smem);

    const int tid  = threadIdx.x;
    const int lane = tid & 31;
    const int wid  = tid >> 5;
    const int wm   = wid >> 2;
    const int wn   = wid & 3;
    const int row0 = blockIdx.x * 64;

    const int mat = lane >> 3, r8 = lane & 7;
    const uint32_t aoff =
        (uint32_t)((wm * 16 + (mat & 1) * 8 + r8) * AROWB + (mat >> 1) * 16);
    uint32_t boff[2];
#pragma unroll
    for (int nt = 0; nt < 2; nt++)
        boff[nt] = (uint32_t)((wn * 32 + nt * 16 + (mat >> 1) * 8 + r8) * AROWB +
                              (mat & 1) * 16);

    const int ar  = tid >> 3;
    const int aks = tid & 7;
    const float* agp = A + (size_t)(row0 + ar) * 4096 + aks * 8;
    const uint32_t adof = (uint32_t)(ar * AROWB + aks * 16);

    const char* bhp = (const char*)Bhi;
    const char* blp = (const char*)Blo;

    float acc[4][4];
#pragma unroll
    for (int j = 0; j < 4; j++)
#pragma unroll
        for (int c = 0; c < 4; c++) acc[j][c] = 0.0f;

    float4 av0, av1;

    {
#pragma unroll
        for (int q = 0; q < 2; q++) {
            int idx = tid + q * 512;
            int brow = idx >> 3, seg = idx & 7;
            uint32_t dof = (uint32_t)(brow * AROWB + seg * 16);
            size_t gof = (size_t)brow * 8192 + seg * 16;
            cp16(sbase + S_BHI + dof, bhp + gof);
            cp16(sbase + S_BLO + dof, blp + gof);
        }
        cp_commit();
        av0 = *(const float4*)(agp);
        av1 = *(const float4*)(agp + 4);
        uint4 hv, lv;
        split8(av0, av1, hv, lv);
        *(uint4*)(smem + S_AHI + adof) = hv;
        *(uint4*)(smem + S_ALO + adof) = lv;
    }

    for (int i = 0; i < 64; i++) {
        const int s = i & 1;
        const uint32_t st = sbase + s * LSTAGE;
        const uint32_t nst = sbase + (s ^ 1) * LSTAGE;
        char* nst_gen = smem + (s ^ 1) * LSTAGE;

        cp_wait0();
        __syncthreads();

        if (i < 63) {
            const size_t kb = (size_t)(i + 1) * 128;
#pragma unroll
            for (int q = 0; q < 2; q++) {
                int idx = tid + q * 512;
                int brow = idx >> 3, seg = idx & 7;
                uint32_t dof = (uint32_t)(brow * AROWB + seg * 16);
                size_t gof = (size_t)brow * 8192 + kb + seg * 16;
                cp16(nst + S_BHI + dof, bhp + gof);
                cp16(nst + S_BLO + dof, blp + gof);
            }
            cp_commit();
            const float* ap = agp + (size_t)(i + 1) * 64;
            av0 = *(const float4*)(ap);
            av1 = *(const float4*)(ap + 4);
        }

#pragma unroll
        for (int kk = 0; kk < 4; kk++) {
            const uint32_t kb = (uint32_t)(kk * 32);
            uint32_t ah[4], al[4], bh[2][4], bl[2][4];
            ldsm_x4(ah[0], ah[1], ah[2], ah[3], st + S_AHI + aoff + kb);
            ldsm_x4(al[0], al[1], al[2], al[3], st + S_ALO + aoff + kb);
#pragma unroll
            for (int nt = 0; nt < 2; nt++) {
                ldsm_x4(bh[nt][0], bh[nt][1], bh[nt][2], bh[nt][3],
                        st + S_BHI + boff[nt] + kb);
                ldsm_x4(bl[nt][0], bl[nt][1], bl[nt][2], bl[nt][3],
                        st + S_BLO + boff[nt] + kb);
            }
#pragma unroll
            for (int j = 0; j < 4; j++) {
                const int nt = j >> 1, p = (j & 1) * 2;
                uint32_t bhr[2] = {bh[nt][p], bh[nt][p + 1]};
                uint32_t blr[2] = {bl[nt][p], bl[nt][p + 1]};
                mma16816(acc[j], ah, bhr);
                mma16816(acc[j], ah, blr);
                mma16816(acc[j], al, bhr);
            }
        }

        if (i < 63) {
            uint4 hv, lv;
            split8(av0, av1, hv, lv);
            *(uint4*)(nst_gen + S_AHI + adof) = hv;
            *(uint4*)(nst_gen + S_ALO + adof) = lv;
        }
    }

    const int row = row0 + wm * 16 + (lane >> 2);
#pragma unroll
    for (int j = 0; j < 4; j++) {
        const int col = wn * 32 + j * 8 + (lane & 3) * 2;
#pragma unroll
        for (int c = 0; c < 4; c++) {
            const int rr = row + (c >> 1) * 8;
            const int cc = col + (c & 1);
            if (cc < 100)
                C[(size_t)rr * 100 + cc] =
                    fmaxf(acc[j][c] + __ldg(bias + cc), 0.0f);
        }
    }
}

// ----------------------------- tree (feature-major, f32x2, k-split) --------
#define ST 36
#define TBUF (100 * ST)

// Weight from global (__ldg) — used by stage1 (large grid hides latency).
template <int MO>
__device__ __forceinline__ void level_ks(const float4* __restrict__ Wq4,
                                         float bn, int n, int h,
                                         const float* __restrict__ Xs,
                                         float* __restrict__ Ys,
                                         ull* __restrict__ Ps) {
    ull acc[MO];
    if (n < 100) {
#pragma unroll
        for (int j = 0; j < MO; j++) acc[j] = 0ull;
        const int kk0 = h * 25;
        for (int kk = kk0; kk < kk0 + 25; kk++) {
            float4 w = __ldg(Wq4 + kk * 100 + n);
            const ull wA = pack2(w.x, w.y);
            const ull wB = pack2(w.z, w.w);
            const ull* XA = (const ull*)(Xs + (2 * kk) * ST);
            const ull* XB = (const ull*)(Xs + (2 * kk + 1) * ST);
#pragma unroll
            for (int j = 0; j < MO; j++) {
                fma2(acc[j], wA, XA[j]);
                fma2(acc[j], wB, XB[j]);
            }
        }
        if (h == 1) {
#pragma unroll
            for (int j = 0; j < MO; j++) Ps[n * MO + j] = acc[j];
        }
    }
    __syncthreads();
    if (h == 0 && n < 100) {
#pragma unroll
        for (int j = 0; j < MO; j++) {
            float lo0, hi0, lo1, hi1;
            unpack2(acc[j], lo0, hi0);
            unpack2(Ps[n * MO + j], lo1, hi1);
            Ys[n * ST + j] = fmaxf(lo0 + hi0 + lo1 + hi1 + bn, 0.0f);
        }
    }
    __syncthreads();
}

// Weight from shared memory — used by the small-grid tail stages.
template <int MO>
__device__ __forceinline__ void level_ks_sm(const float4* __restrict__ Wqs,
                                            float bn, int n, int h,
                                            const float* __restrict__ Xs,
                                            float* __restrict__ Ys,
                                            ull* __restrict__ Ps) {
    ull acc[MO];
    if (n < 100) {
#pragma unroll
        for (int j = 0; j < MO; j++) acc[j] = 0ull;
        const int kk0 = h * 25;
        for (int kk = kk0; kk < kk0 + 25; kk++) {
            float4 w = Wqs[kk * 100 + n];
            const ull wA = pack2(w.x, w.y);
            const ull wB = pack2(w.z, w.w);
            const ull* XA = (const ull*)(Xs + (2 * kk) * ST);
            const ull* XB = (const ull*)(Xs + (2 * kk + 1) * ST);
#pragma unroll
            for (int j = 0; j < MO; j++) {
                fma2(acc[j], wA, XA[j]);
                fma2(acc[j], wB, XB[j]);
            }
        }
        if (h == 1) {
#pragma unroll
            for (int j = 0; j < MO; j++) Ps[n * MO + j] = acc[j];
        }
    }
    __syncthreads();
    if (h == 0 && n < 100) {
#pragma unroll
        for (int j = 0; j < MO; j++) {
            float lo0, hi0, lo1, hi1;
            unpack2(acc[j], lo0, hi0);
            unpack2(Ps[n * MO + j], lo1, hi1);
            Ys[n * ST + j] = fmaxf(lo0 + hi0 + lo1 + hi1 + bn, 0.0f);
        }
    }
    __syncthreads();
}

// stage1: 256 blocks x 32 leaf rows -> 5 levels -> T1[feat][256] (unchanged)
__global__ __launch_bounds__(256)
void tree_stage1(const float* __restrict__ h0, float* __restrict__ T1,
                 const float* __restrict__ Wq, const float* __restrict__ b) {
    __shared__ float sm[2 * TBUF];
    __shared__ ull Ps[100 * 16];
    const int n = threadIdx.x & 127;
    const int h = threadIdx.x >> 7;
    const float bn = (n < 100) ? __ldg(b + n) : 0.0f;
    const float4* Wq4 = (const float4*)Wq;

    const float* in = h0 + (size_t)blockIdx.x * 3200;
    for (int i = threadIdx.x; i < 3200; i += 256) {
        int r = i / 100, f = i - r * 100;
        sm[f * ST + r] = in[i];
    }
    __syncthreads();

    float* Ab = sm;
    float* Bb = sm + TBUF;
    level_ks<16>(Wq4, bn, n, h, Ab, Bb, Ps);
    level_ks<8>(Wq4, bn, n, h, Bb, Ab, Ps);
    level_ks<4>(Wq4, bn, n, h, Ab, Bb, Ps);
    level_ks<2>(Wq4, bn, n, h, Bb, Ab, Ps);
    level_ks<1>(Wq4, bn, n, h, Ab, Bb, Ps);
    if (threadIdx.x < 100) T1[threadIdx.x * 256 + blockIdx.x] = Bb[threadIdx.x * ST];
}

// dyn smem layout for tail stages: Wqs[5000 float4] | bufs[2*TBUF f32] | Ps[1600 ull]
#define TAIL_W_BYTES   (5000 * 16)                       // 80000
#define TAIL_BUF_BYTES (2 * TBUF * 4)                    // 28800
#define TAIL_PS_BYTES  (1600 * 8)                        // 12800
#define TAIL_SMEM      (TAIL_W_BYTES + TAIL_BUF_BYTES + TAIL_PS_BYTES)  // 121600

// stage2: 8 blocks x 32 cols -> 5 levels -> T2[feat][8] (smem weights)
__global__ __launch_bounds__(256)
void tree_stage2(const float* __restrict__ T1, float* __restrict__ T2,
                 const float* __restrict__ Wq, const float* __restrict__ b) {
    extern __shared__ char dsm[];
    float4* Wqs = (float4*)dsm;
    float* sm   = (float*)(dsm + TAIL_W_BYTES);
    ull*   Ps   = (ull*)(dsm + TAIL_W_BYTES + TAIL_BUF_BYTES);

    const int n = threadIdx.x & 127;
    const int h = threadIdx.x >> 7;
    const float bn = (n < 100) ? __ldg(b + n) : 0.0f;

    const float4* Wg = (const float4*)Wq;
    for (int i = threadIdx.x; i < 5000; i += 256) Wqs[i] = __ldg(Wg + i);
    for (int i = threadIdx.x; i < 3200; i += 256) {
        int f = i >> 5, c = i & 31;
        sm[f * ST + c] = T1[f * 256 + blockIdx.x * 32 + c];
    }
    __syncthreads();

    float* Ab = sm;
    float* Bb = sm + TBUF;
    level_ks_sm<16>(Wqs, bn, n, h, Ab, Bb, Ps);
    level_ks_sm<8>(Wqs, bn, n, h, Bb, Ab, Ps);
    level_ks_sm<4>(Wqs, bn, n, h, Ab, Bb, Ps);
    level_ks_sm<2>(Wqs, bn, n, h, Bb, Ab, Ps);
    level_ks_sm<1>(Wqs, bn, n, h, Ab, Bb, Ps);
    if (threadIdx.x < 100) T2[threadIdx.x * 8 + blockIdx.x] = Bb[threadIdx.x * ST];
}

// stage3: 1 block, 8 cols -> 3 levels -> projection (smem weights)
__global__ __launch_bounds__(256)
void tree_stage3(const float* __restrict__ T2, float* __restrict__ out,
                 const float* __restrict__ Wq, const float* __restrict__ b,
                 const float* __restrict__ Wp, const float* __restrict__ bp) {
    extern __shared__ char dsm[];
    float4* Wqs = (float4*)dsm;
    float* sm   = (float*)(dsm + TAIL_W_BYTES);
    ull*   Ps   = (ull*)(dsm + TAIL_W_BYTES + TAIL_BUF_BYTES);

    const int n = threadIdx.x & 127;
    const int h = threadIdx.x >> 7;
    const float bn = (n < 100) ? __ldg(b + n) : 0.0f;

    const float4* Wg = (const float4*)Wq;
    for (int i = threadIdx.x; i < 5000; i += 256) Wqs[i] = __ldg(Wg + i);
    for (int i = threadIdx.x; i < 800; i += 256) {
        int f = i >> 3, c = i & 7;
        sm[f * ST + c] = T2[i];
    }
    __syncthreads();

    float* Ab = sm;
    float* Bb = sm + TBUF;
    level_ks_sm<4>(Wqs, bn, n, h, Ab, Bb, Ps);
    level_ks_sm<2>(Wqs, bn, n, h, Bb, Ab, Ps);
    level_ks_sm<1>(Wqs, bn, n, h, Ab, Bb, Ps);
    if (threadIdx.x < 64) {
        const int c = threadIdx.x >> 5;
        const int lane = threadIdx.x & 31;
        float s = 0.0f;
        for (int k = lane; k < 100; k += 32) s += __ldg(Wp + c * 100 + k) * Bb[k * ST];
#pragma unroll
        for (int o = 16; o > 0; o >>= 1) s += __shfl_down_sync(0xffffffffu, s, o);
        if (lane == 0) out[c] = s + __ldg(bp + c);
    }
}

// ------------------------------ launch -------------------------------------
extern "C" void kernel_launch(void* const* d_in, const int* in_sizes, int n_in,
                              void* d_out, int out_size) {
    const float* leaf = (const float*)d_in[0];  // [8192, 4096]
    const float* We   = (const float*)d_in[1];  // [100, 4096]
    const float* be   = (const float*)d_in[2];  // [100]
    const float* W    = (const float*)d_in[3];  // [100, 200]
    const float* b    = (const float*)d_in[4];  // [100]
    const float* Wp   = (const float*)d_in[5];  // [2, 100]
    const float* bp   = (const float*)d_in[6];  // [2]
    float* out = (float*)d_out;

    __nv_bfloat16 *Bhi, *Blo;
    float *Wq, *h0, *T1, *T2;
    cudaGetSymbolAddress((void**)&Bhi, g_Bhi);
    cudaGetSymbolAddress((void**)&Blo, g_Blo);
    cudaGetSymbolAddress((void**)&Wq, g_Wq);
    cudaGetSymbolAddress((void**)&h0, g_h0);
    cudaGetSymbolAddress((void**)&T1, g_T1);
    cudaGetSymbolAddress((void**)&T2, g_T2);

    static int attr_set = 0;
    if (!attr_set) {
        cudaFuncSetAttribute(leaf_gemm_mma, cudaFuncAttributeMaxDynamicSharedMemorySize,
                             LEAF_SMEM);
        cudaFuncSetAttribute(tree_stage2, cudaFuncAttributeMaxDynamicSharedMemorySize,
                             TAIL_SMEM);
        cudaFuncSetAttribute(tree_stage3, cudaFuncAttributeMaxDynamicSharedMemorySize,
                             TAIL_SMEM);
        attr_set = 1;
    }

    prep_all<<<(128 * 4096 + 5000 + 255) / 256, 256>>>(We, Bhi, Blo, W, Wq);

    leaf_gemm_mma<<<128, 512, LEAF_SMEM>>>(leaf, Bhi, Blo, be, h0);

    tree_stage1<<<256, 256>>>(h0, T1, Wq, b);
    tree_stage2<<<8, 256, TAIL_SMEM>>>(T1, T2, Wq, b);
    tree_stage3<<<1, 256, TAIL_SMEM>>>(T2, out, Wq, b, Wp, bp);
}

// round 17
// speedup vs baseline: 1.0111x; 1.0111x over previous
#include <cuda_runtime.h>
#include <cuda_bf16.h>
#include <cstdint>

// ===========================================================================
// Tree-RNN round 16 = the 161.2us R14 kernel + grid padding to >=148 blocks
// on every kernel (B300 pSmIssueThrottleCtrl throttles low-grid kernels with
// large bodies; the throttle vanishes at grid>=148 per B300_MICROARCH).
// ===========================================================================

typedef unsigned long long ull;

// ----------------------------- scratch ------------------------------------
__device__ __nv_bfloat16 g_Bhi[128 * 4096];
__device__ __nv_bfloat16 g_Blo[128 * 4096];
__device__ float g_Wq[50 * 100 * 4];
__device__ float g_h0[8192 * 100];
__device__ float g_T1[100 * 256];
__device__ float g_T2[100 * 8];

// ----------------------------- helpers ------------------------------------
__device__ __forceinline__ void cp16(uint32_t saddr, const void* g) {
    asm volatile("cp.async.cg.shared.global [%0], [%1], 16;" :: "r"(saddr), "l"(g));
}
__device__ __forceinline__ void cp_commit() { asm volatile("cp.async.commit_group;"); }
__device__ __forceinline__ void cp_wait0()  { asm volatile("cp.async.wait_group 0;"); }

__device__ __forceinline__ void ldsm_x4(uint32_t& r0, uint32_t& r1, uint32_t& r2,
                                        uint32_t& r3, uint32_t addr) {
    asm volatile("ldmatrix.sync.aligned.m8n8.x4.shared.b16 {%0,%1,%2,%3}, [%4];"
                 : "=r"(r0), "=r"(r1), "=r"(r2), "=r"(r3) : "r"(addr));
}
__device__ __forceinline__ void mma16816(float* c, const uint32_t* a, const uint32_t* b) {
    asm volatile(
        "mma.sync.aligned.m16n8k16.row.col.f32.bf16.bf16.f32 "
        "{%0,%1,%2,%3}, {%4,%5,%6,%7}, {%8,%9}, {%0,%1,%2,%3};"
        : "+f"(c[0]), "+f"(c[1]), "+f"(c[2]), "+f"(c[3])
        : "r"(a[0]), "r"(a[1]), "r"(a[2]), "r"(a[3]), "r"(b[0]), "r"(b[1]));
}

__device__ __forceinline__ void split8(float4 a, float4 b, uint4& hv, uint4& lv) {
    __nv_bfloat162 h0 = __float22bfloat162_rn(make_float2(a.x, a.y));
    __nv_bfloat162 h1 = __float22bfloat162_rn(make_float2(a.z, a.w));
    __nv_bfloat162 h2 = __float22bfloat162_rn(make_float2(b.x, b.y));
    __nv_bfloat162 h3 = __float22bfloat162_rn(make_float2(b.z, b.w));
    float2 f0 = __bfloat1622float2(h0), f1 = __bfloat1622float2(h1);
    float2 f2 = __bfloat1622float2(h2), f3 = __bfloat1622float2(h3);
    __nv_bfloat162 l0 = __float22bfloat162_rn(make_float2(a.x - f0.x, a.y - f0.y));
    __nv_bfloat162 l1 = __float22bfloat162_rn(make_float2(a.z - f1.x, a.w - f1.y));
    __nv_bfloat162 l2 = __float22bfloat162_rn(make_float2(b.x - f2.x, b.y - f2.y));
    __nv_bfloat162 l3 = __float22bfloat162_rn(make_float2(b.z - f3.x, b.w - f3.y));
    hv = make_uint4(*(uint32_t*)&h0, *(uint32_t*)&h1, *(uint32_t*)&h2, *(uint32_t*)&h3);
    lv = make_uint4(*(uint32_t*)&l0, *(uint32_t*)&l1, *(uint32_t*)&l2, *(uint32_t*)&l3);
}

__device__ __forceinline__ ull pack2(float lo, float hi) {
    ull r;
    asm("mov.b64 %0, {%1, %2};" : "=l"(r) : "f"(lo), "f"(hi));
    return r;
}
__device__ __forceinline__ void fma2(ull& d, ull a, ull b) {
    asm("fma.rn.f32x2 %0, %1, %2, %0;" : "+l"(d) : "l"(a), "l"(b));
}
__device__ __forceinline__ void unpack2(ull v, float& lo, float& hi) {
    asm("mov.b64 {%0, %1}, %2;" : "=f"(lo), "=f"(hi) : "l"(v));
}

// ----------------------------- prep (merged) -------------------------------
__global__ void prep_all(const float* __restrict__ We,
                         __nv_bfloat16* __restrict__ bhi,
                         __nv_bfloat16* __restrict__ blo,
                         const float* __restrict__ W,
                         float* __restrict__ Wq) {
    int idx = blockIdx.x * blockDim.x + threadIdx.x;
    if (idx < 128 * 4096) {
        int n = idx >> 12;
        float v = (n < 100) ? We[idx] : 0.0f;
        __nv_bfloat16 h = __float2bfloat16(v);
        bhi[idx] = h;
        blo[idx] = __float2bfloat16(v - __bfloat162float(h));
    } else if (idx < 128 * 4096 + 5000) {
        int i = idx - 128 * 4096;
        int kk = i / 100, n = i % 100;
        float4 q;
        q.x = W[n * 200 + 2 * kk];
        q.y = W[n * 200 + 100 + 2 * kk];
        q.z = W[n * 200 + 2 * kk + 1];
        q.w = W[n * 200 + 101 + 2 * kk];
        *(float4*)(Wq + i * 4) = q;
    }
}

// ----------------------------- leaf GEMM (proven config, grid-padded) ------
#define AROWB     144
#define S_AHI     0
#define S_ALO     (64 * AROWB)
#define S_BHI     (2 * 64 * AROWB)
#define S_BLO     (S_BHI + 128 * AROWB)
#define LSTAGE    (S_BLO + 128 * AROWB)     // 55296
#define LEAF_SMEM (2 * LSTAGE)              // 110592

__global__ __launch_bounds__(512)
void leaf_gemm_mma(const float* __restrict__ A,
                   const __nv_bfloat16* __restrict__ Bhi,
                   const __nv_bfloat16* __restrict__ Blo,
                   const float* __restrict__ bias,
                   float* __restrict__ C) {
    if (blockIdx.x >= 128) return;   // grid padded to >=148 for throttle escape
    extern __shared__ char smem[];
    const uint32_t sbase = (uint32_t)__cvta_generic_to_shared(smem);

    const int tid  = threadIdx.x;
    const int lane = tid & 31;
    const int wid  = tid >> 5;
    const int wm   = wid >> 2;
    const int wn   = wid & 3;
    const int row0 = blockIdx.x * 64;

    const int mat = lane >> 3, r8 = lane & 7;
    const uint32_t aoff =
        (uint32_t)((wm * 16 + (mat & 1) * 8 + r8) * AROWB + (mat >> 1) * 16);
    uint32_t boff[2];
#pragma unroll
    for (int nt = 0; nt < 2; nt++)
        boff[nt] = (uint32_t)((wn * 32 + nt * 16 + (mat >> 1) * 8 + r8) * AROWB +
                              (mat & 1) * 16);

    const int ar  = tid >> 3;
    const int aks = tid & 7;
    const float* agp = A + (size_t)(row0 + ar) * 4096 + aks * 8;
    const uint32_t adof = (uint32_t)(ar * AROWB + aks * 16);

    const char* bhp = (const char*)Bhi;
    const char* blp = (const char*)Blo;

    float acc[4][4];
#pragma unroll
    for (int j = 0; j < 4; j++)
#pragma unroll
        for (int c = 0; c < 4; c++) acc[j][c] = 0.0f;

    float4 av0, av1;

    {
#pragma unroll
        for (int q = 0; q < 2; q++) {
            int idx = tid + q * 512;
            int brow = idx >> 3, seg = idx & 7;
            uint32_t dof = (uint32_t)(brow * AROWB + seg * 16);
            size_t gof = (size_t)brow * 8192 + seg * 16;
            cp16(sbase + S_BHI + dof, bhp + gof);
            cp16(sbase + S_BLO + dof, blp + gof);
        }
        cp_commit();
        av0 = *(const float4*)(agp);
        av1 = *(const float4*)(agp + 4);
        uint4 hv, lv;
        split8(av0, av1, hv, lv);
        *(uint4*)(smem + S_AHI + adof) = hv;
        *(uint4*)(smem + S_ALO + adof) = lv;
    }

    for (int i = 0; i < 64; i++) {
        const int s = i & 1;
        const uint32_t st = sbase + s * LSTAGE;
        const uint32_t nst = sbase + (s ^ 1) * LSTAGE;
        char* nst_gen = smem + (s ^ 1) * LSTAGE;

        cp_wait0();
        __syncthreads();

        if (i < 63) {
            const size_t kb = (size_t)(i + 1) * 128;
#pragma unroll
            for (int q = 0; q < 2; q++) {
                int idx = tid + q * 512;
                int brow = idx >> 3, seg = idx & 7;
                uint32_t dof = (uint32_t)(brow * AROWB + seg * 16);
                size_t gof = (size_t)brow * 8192 + kb + seg * 16;
                cp16(nst + S_BHI + dof, bhp + gof);
                cp16(nst + S_BLO + dof, blp + gof);
            }
            cp_commit();
            const float* ap = agp + (size_t)(i + 1) * 64;
            av0 = *(const float4*)(ap);
            av1 = *(const float4*)(ap + 4);
        }

#pragma unroll
        for (int kk = 0; kk < 4; kk++) {
            const uint32_t kb = (uint32_t)(kk * 32);
            uint32_t ah[4], al[4], bh[2][4], bl[2][4];
            ldsm_x4(ah[0], ah[1], ah[2], ah[3], st + S_AHI + aoff + kb);
            ldsm_x4(al[0], al[1], al[2], al[3], st + S_ALO + aoff + kb);
#pragma unroll
            for (int nt = 0; nt < 2; nt++) {
                ldsm_x4(bh[nt][0], bh[nt][1], bh[nt][2], bh[nt][3],
                        st + S_BHI + boff[nt] + kb);
                ldsm_x4(bl[nt][0], bl[nt][1], bl[nt][2], bl[nt][3],
                        st + S_BLO + boff[nt] + kb);
            }
#pragma unroll
            for (int j = 0; j < 4; j++) {
                const int nt = j >> 1, p = (j & 1) * 2;
                uint32_t bhr[2] = {bh[nt][p], bh[nt][p + 1]};
                uint32_t blr[2] = {bl[nt][p], bl[nt][p + 1]};
                mma16816(acc[j], ah, bhr);
                mma16816(acc[j], ah, blr);
                mma16816(acc[j], al, bhr);
            }
        }

        if (i < 63) {
            uint4 hv, lv;
            split8(av0, av1, hv, lv);
            *(uint4*)(nst_gen + S_AHI + adof) = hv;
            *(uint4*)(nst_gen + S_ALO + adof) = lv;
        }
    }

    const int row = row0 + wm * 16 + (lane >> 2);
#pragma unroll
    for (int j = 0; j < 4; j++) {
        const int col = wn * 32 + j * 8 + (lane & 3) * 2;
#pragma unroll
        for (int c = 0; c < 4; c++) {
            const int rr = row + (c >> 1) * 8;
            const int cc = col + (c & 1);
            if (cc < 100)
                C[(size_t)rr * 100 + cc] =
                    fmaxf(acc[j][c] + __ldg(bias + cc), 0.0f);
        }
    }
}

// ----------------------------- tree (feature-major, f32x2, k-split) --------
#define ST 36
#define TBUF (100 * ST)

template <int MO>
__device__ __forceinline__ void level_ks(const float4* __restrict__ Wq4,
                                         float bn, int n, int h,
                                         const float* __restrict__ Xs,
                                         float* __restrict__ Ys,
                                         ull* __restrict__ Ps) {
    ull acc[MO];
    if (n < 100) {
#pragma unroll
        for (int j = 0; j < MO; j++) acc[j] = 0ull;
        const int kk0 = h * 25;
        for (int kk = kk0; kk < kk0 + 25; kk++) {
            float4 w = __ldg(Wq4 + kk * 100 + n);
            const ull wA = pack2(w.x, w.y);
            const ull wB = pack2(w.z, w.w);
            const ull* XA = (const ull*)(Xs + (2 * kk) * ST);
            const ull* XB = (const ull*)(Xs + (2 * kk + 1) * ST);
#pragma unroll
            for (int j = 0; j < MO; j++) {
                fma2(acc[j], wA, XA[j]);
                fma2(acc[j], wB, XB[j]);
            }
        }
        if (h == 1) {
#pragma unroll
            for (int j = 0; j < MO; j++) Ps[n * MO + j] = acc[j];
        }
    }
    __syncthreads();
    if (h == 0 && n < 100) {
#pragma unroll
        for (int j = 0; j < MO; j++) {
            float lo0, hi0, lo1, hi1;
            unpack2(acc[j], lo0, hi0);
            unpack2(Ps[n * MO + j], lo1, hi1);
            Ys[n * ST + j] = fmaxf(lo0 + hi0 + lo1 + hi1 + bn, 0.0f);
        }
    }
    __syncthreads();
}

// stage1: 256 blocks x 32 leaf rows -> 5 levels -> T1[feat][256]
__global__ __launch_bounds__(256)
void tree_stage1(const float* __restrict__ h0, float* __restrict__ T1,
                 const float* __restrict__ Wq, const float* __restrict__ b) {
    __shared__ float sm[2 * TBUF];
    __shared__ ull Ps[100 * 16];
    const int n = threadIdx.x & 127;
    const int h = threadIdx.x >> 7;
    const float bn = (n < 100) ? __ldg(b + n) : 0.0f;
    const float4* Wq4 = (const float4*)Wq;

    const float* in = h0 + (size_t)blockIdx.x * 3200;
    for (int i = threadIdx.x; i < 3200; i += 256) {
        int r = i / 100, f = i - r * 100;
        sm[f * ST + r] = in[i];
    }
    __syncthreads();

    float* Ab = sm;
    float* Bb = sm + TBUF;
    level_ks<16>(Wq4, bn, n, h, Ab, Bb, Ps);
    level_ks<8>(Wq4, bn, n, h, Bb, Ab, Ps);
    level_ks<4>(Wq4, bn, n, h, Ab, Bb, Ps);
    level_ks<2>(Wq4, bn, n, h, Bb, Ab, Ps);
    level_ks<1>(Wq4, bn, n, h, Ab, Bb, Ps);
    if (threadIdx.x < 100) T1[threadIdx.x * 256 + blockIdx.x] = Bb[threadIdx.x * ST];
}

// stage2: 8 working blocks (grid padded to 148) x 32 cols -> 5 levels
__global__ __launch_bounds__(256)
void tree_stage2(const float* __restrict__ T1, float* __restrict__ T2,
                 const float* __restrict__ Wq, const float* __restrict__ b) {
    if (blockIdx.x >= 8) return;
    __shared__ float sm[2 * TBUF];
    __shared__ ull Ps[100 * 16];
    const int n = threadIdx.x & 127;
    const int h = threadIdx.x >> 7;
    const float bn = (n < 100) ? __ldg(b + n) : 0.0f;
    const float4* Wq4 = (const float4*)Wq;

    for (int i = threadIdx.x; i < 3200; i += 256) {
        int f = i >> 5, c = i & 31;
        sm[f * ST + c] = T1[f * 256 + blockIdx.x * 32 + c];
    }
    __syncthreads();

    float* Ab = sm;
    float* Bb = sm + TBUF;
    level_ks<16>(Wq4, bn, n, h, Ab, Bb, Ps);
    level_ks<8>(Wq4, bn, n, h, Bb, Ab, Ps);
    level_ks<4>(Wq4, bn, n, h, Ab, Bb, Ps);
    level_ks<2>(Wq4, bn, n, h, Bb, Ab, Ps);
    level_ks<1>(Wq4, bn, n, h, Ab, Bb, Ps);
    if (threadIdx.x < 100) T2[threadIdx.x * 8 + blockIdx.x] = Bb[threadIdx.x * ST];
}

// stage3: 1 working block (grid padded to 148), 8 cols -> 3 levels -> proj
__global__ __launch_bounds__(256)
void tree_stage3(const float* __restrict__ T2, float* __restrict__ out,
                 const float* __restrict__ Wq, const float* __restrict__ b,
                 const float* __restrict__ Wp, const float* __restrict__ bp) {
    if (blockIdx.x != 0) return;
    __shared__ float sm[2 * TBUF];
    __shared__ ull Ps[100 * 16];
    const int n = threadIdx.x & 127;
    const int h = threadIdx.x >> 7;
    const float bn = (n < 100) ? __ldg(b + n) : 0.0f;
    const float4* Wq4 = (const float4*)Wq;

    for (int i = threadIdx.x; i < 800; i += 256) {
        int f = i >> 3, c = i & 7;
        sm[f * ST + c] = T2[i];
    }
    __syncthreads();

    float* Ab = sm;
    float* Bb = sm + TBUF;
    level_ks<4>(Wq4, bn, n, h, Ab, Bb, Ps);
    level_ks<2>(Wq4, bn, n, h, Bb, Ab, Ps);
    level_ks<1>(Wq4, bn, n, h, Ab, Bb, Ps);
    if (threadIdx.x < 64) {
        const int c = threadIdx.x >> 5;
        const int lane = threadIdx.x & 31;
        float s = 0.0f;
        for (int k = lane; k < 100; k += 32) s += __ldg(Wp + c * 100 + k) * Bb[k * ST];
#pragma unroll
        for (int o = 16; o > 0; o >>= 1) s += __shfl_down_sync(0xffffffffu, s, o);
        if (lane == 0) out[c] = s + __ldg(bp + c);
    }
}

// ------------------------------ launch -------------------------------------
extern "C" void kernel_launch(void* const* d_in, const int* in_sizes, int n_in,
                              void* d_out, int out_size) {
    const float* leaf = (const float*)d_in[0];  // [8192, 4096]
    const float* We   = (const float*)d_in[1];  // [100, 4096]
    const float* be   = (const float*)d_in[2];  // [100]
    const float* W    = (const float*)d_in[3];  // [100, 200]
    const float* b    = (const float*)d_in[4];  // [100]
    const float* Wp   = (const float*)d_in[5];  // [2, 100]
    const float* bp   = (const float*)d_in[6];  // [2]
    float* out = (float*)d_out;

    __nv_bfloat16 *Bhi, *Blo;
    float *Wq, *h0, *T1, *T2;
    cudaGetSymbolAddress((void**)&Bhi, g_Bhi);
    cudaGetSymbolAddress((void**)&Blo, g_Blo);
    cudaGetSymbolAddress((void**)&Wq, g_Wq);
    cudaGetSymbolAddress((void**)&h0, g_h0);
    cudaGetSymbolAddress((void**)&T1, g_T1);
    cudaGetSymbolAddress((void**)&T2, g_T2);

    static int attr_set = 0;
    if (!attr_set) {
        cudaFuncSetAttribute(leaf_gemm_mma, cudaFuncAttributeMaxDynamicSharedMemorySize,
                             LEAF_SMEM);
        attr_set = 1;
    }

    prep_all<<<(128 * 4096 + 5000 + 255) / 256, 256>>>(We, Bhi, Blo, W, Wq);

    leaf_gemm_mma<<<160, 512, LEAF_SMEM>>>(leaf, Bhi, Blo, be, h0);

    tree_stage1<<<256, 256>>>(h0, T1, Wq, b);
    tree_stage2<<<148, 256>>>(T1, T2, Wq, b);
    tree_stage3<<<148, 256>>>(T2, out, Wq, b, Wp, bp);
}